// round 15
// baseline (speedup 1.0000x reference)
#include <cuda_runtime.h>
#include <cuda_bf16.h>

// Problem constants (fixed by the dataset)
#define MAXN 100000
#define MAXE 3200000
#define INC1 64
#define HIDC 128
#define OUTC2 64
#define CAP 128              // per-node bucket capacity; in-deg ~ Poisson(32), P(>128) ~ 1e-40

// Packed fp32x2 ops (sm_100+; ptxas never emits these from C++)
#define ADDF32X2(acc, a) \
    asm("add.rn.f32x2 %0, %0, %1;" : "+l"(acc) : "l"(a))
#define FMAF32X2(acc, x, w) \
    asm("fma.rn.f32x2 %0, %1, %2, %0;" : "+l"(acc) : "l"(x), "l"(w))
#define UNPACK2(lo, hi, p) \
    asm("mov.b64 {%0, %1}, %2;" : "=f"(lo), "=f"(hi) : "l"(p))

// ---------------- device scratch (no allocations allowed) ----------------
__device__ float g_buf_o1[MAXN * HIDC];  // relu(layer1 output)            [N,128]
__device__ float g_buf_xs[MAXN * INC1];  // dinv*x, later reused for g2     [N,64]
__device__ float g_buf_a [MAXN * INC1];  // aggregated xs                   [N,64]
__device__ int   g_cursor[MAXN];         // absolute write cursor per bucket
__device__ int   g_col[MAXN * CAP];      // bucketed adjacency (src ids)
__device__ float g_dinv[MAXN];

// ---------------- bucket build ----------------
__global__ void init_cursor_kernel(int n) {
    int i = blockIdx.x * blockDim.x + threadIdx.x;
    if (i < n) g_cursor[i] = i * CAP;
}

// 4 edges per thread via int4 loads; atomic cursor allocates bucket slots.
__global__ void fill_kernel(const int* __restrict__ src,
                            const int* __restrict__ dst, int E) {
    int i = blockIdx.x * blockDim.x + threadIdx.x;
    int e = i << 2;
    if (e + 3 < E) {
        int4 s4 = *reinterpret_cast<const int4*>(src + e);
        int4 d4 = *reinterpret_cast<const int4*>(dst + e);
        g_col[atomicAdd(&g_cursor[d4.x], 1)] = s4.x;
        g_col[atomicAdd(&g_cursor[d4.y], 1)] = s4.y;
        g_col[atomicAdd(&g_cursor[d4.z], 1)] = s4.z;
        g_col[atomicAdd(&g_cursor[d4.w], 1)] = s4.w;
    } else if (e < E) {
        for (int k = e; k < E; k++)
            g_col[atomicAdd(&g_cursor[dst[k]], 1)] = src[k];
    }
}

// ---------------- xs = dinv .* x  (also materializes dinv from cursor) ----------------
__global__ void scale_x_kernel(const float* __restrict__ X, float* __restrict__ XS, int n) {
    int i = blockIdx.x * blockDim.x + threadIdx.x;      // one float4 per thread
    if (i >= n * 16) return;
    int row = i >> 4;
    int cnt = g_cursor[row] - row * CAP;                // in-degree (no self loop)
    float di = rsqrtf((float)(cnt + 1));
    if ((i & 15) == 0) g_dinv[row] = di;
    float4 v = ((const float4*)X)[i];
    v.x *= di; v.y *= di; v.z *= di; v.w *= di;
    ((float4*)XS)[i] = v;
}

// ---------------- Aggregation (bucket gather), one warp per node, 64 ch ----------------
// R13-measured-best: int4 index fetch, software pipelining, packed f32x2 adds.
template <int EPI>
__global__ void __launch_bounds__(256)
agg64_kernel(const float* __restrict__ G, const float* __restrict__ b,
             float* __restrict__ O, int n) {
    int warp = (blockIdx.x * blockDim.x + threadIdx.x) >> 5;
    int lane = threadIdx.x & 31;
    if (warp >= n) return;
    const int d = warp;
    const unsigned long long* __restrict__ Gv = (const unsigned long long*)G;
    unsigned long long acc = Gv[d * 32 + lane];          // self loop (packed f32x2)
    int e = d * CAP;
    const int end = g_cursor[d];
    int4 s;
    bool have = (e + 4 <= end);
    if (have) s = *reinterpret_cast<const int4*>(g_col + e);
    while (have) {
        int4 c = s;
        e += 4;
        have = (e + 4 <= end);
        if (have) s = *reinterpret_cast<const int4*>(g_col + e);
        unsigned long long a0 = Gv[c.x * 32 + lane];
        unsigned long long a1 = Gv[c.y * 32 + lane];
        unsigned long long a2 = Gv[c.z * 32 + lane];
        unsigned long long a3 = Gv[c.w * 32 + lane];
        ADDF32X2(acc, a0);
        ADDF32X2(acc, a1);
        ADDF32X2(acc, a2);
        ADDF32X2(acc, a3);
    }
    for (; e < end; e++) {
        int si = g_col[e];
        unsigned long long a = Gv[si * 32 + lane];
        ADDF32X2(acc, a);
    }
    float2 r;
    UNPACK2(r.x, r.y, acc);
    if (EPI) {
        const float di = g_dinv[d];
        float2 bi = ((const float2*)b)[lane];
        r.x = di * r.x + bi.x;
        r.y = di * r.y + bi.y;
    }
    ((float2*)O)[d * 32 + lane] = r;
}

// ---------------- GEMM, channel-pair packed FFMA2 ----------------
// Thread owns output channels (2tx, 2tx+1). W pair: natural LDS.64 from the
// original Ws layout (lanes 8B-consecutive -> conflict-free). X staged DUPLICATED
// (Xsd[row][2k]=Xsd[row][2k+1]=x) so the {x,x} packed operand is one broadcast
// LDS.64 -- no pack movs. Per k: 1 LDS.64(w) + RR LDS.64(x) + RR FFMA2
// = (1+2RR) issues for 2RR warp-MACs (half of the scalar version).
// EPI=1: relu(dinv*acc + b) ; EPI=0: dinv*acc
template <int INC, int OUTC, int TY, int RR, int RPB, int EPI>
__global__ void __launch_bounds__((OUTC / 2) * TY)
gemm_kernel(const float* __restrict__ X, const float* __restrict__ W,
            const float* __restrict__ b, float* __restrict__ G, int n) {
    const int ROWS = TY * RR;
    const int HC = OUTC / 2;
    __shared__ float Ws[INC * OUTC];
    __shared__ __align__(16) float Xsd[ROWS * 2 * INC];
    const int tx = threadIdx.x;              // channel pair index
    const int ty = threadIdx.y;
    const int tid = ty * HC + tx;
    const int nthr = HC * TY;
    for (int i = tid; i < INC * OUTC; i += nthr) Ws[i] = W[i];
    __syncthreads();
    const int base = blockIdx.x * RPB;
    for (int r0 = 0; r0 < RPB; r0 += ROWS) {
        // stage ROWS rows duplicated: x -> {x,x} adjacent
        for (int i = tid; i < ROWS * INC; i += nthr) {
            int row = i / INC;
            int k = i % INC;
            int rr = base + r0 + row;
            float v = (rr < n) ? X[rr * INC + k] : 0.f;
            *(float2*)&Xsd[row * 2 * INC + 2 * k] = make_float2(v, v);
        }
        __syncthreads();
        unsigned long long acc2[RR];
#pragma unroll
        for (int r = 0; r < RR; r++) acc2[r] = 0ull;   // packed (+0,+0)
#pragma unroll 8
        for (int k = 0; k < INC; k++) {
            unsigned long long wp = *(const unsigned long long*)&Ws[k * OUTC + 2 * tx];
#pragma unroll
            for (int r = 0; r < RR; r++) {
                unsigned long long xp =
                    *(const unsigned long long*)&Xsd[(ty * RR + r) * 2 * INC + 2 * k];
                FMAF32X2(acc2[r], xp, wp);
            }
        }
#pragma unroll
        for (int r = 0; r < RR; r++) {
            int row = base + r0 + ty * RR + r;
            if (row < n) {
                float lo, hi;
                UNPACK2(lo, hi, acc2[r]);
                float di = g_dinv[row];
                float2 o;
                if (EPI) {
                    float2 bi = ((const float2*)b)[tx];
                    o.x = fmaxf(di * lo + bi.x, 0.f);
                    o.y = fmaxf(di * hi + bi.y, 0.f);
                } else {
                    o.x = di * lo;
                    o.y = di * hi;
                }
                *(float2*)&G[row * OUTC + 2 * tx] = o;
            }
        }
        __syncthreads();
    }
}

// ---------------- launch ----------------
extern "C" void kernel_launch(void* const* d_in, const int* in_sizes, int n_in,
                              void* d_out, int out_size) {
    const float* x  = (const float*)d_in[0];
    const int*   ei = (const int*)d_in[1];     // int32 (JAX x64-disabled truncates int64)
    const float* W1 = (const float*)d_in[2];
    const float* b1 = (const float*)d_in[3];
    const float* W2 = (const float*)d_in[4];
    const float* b2 = (const float*)d_in[5];
    float* out = (float*)d_out;

    const int n = in_sizes[0] / INC1;     // 100000
    const int E = in_sizes[1] / 2;        // 3200000
    const int* src = ei;
    const int* dst = ei + E;
    const int e4 = (E + 3) / 4;

    float* d_o1 = nullptr; cudaGetSymbolAddress((void**)&d_o1, g_buf_o1);
    float* d_xs = nullptr; cudaGetSymbolAddress((void**)&d_xs, g_buf_xs);
    float* d_a  = nullptr; cudaGetSymbolAddress((void**)&d_a,  g_buf_a);

    // 1) bucketed adjacency build (no count pass, no scan)
    init_cursor_kernel<<<(n + 255) / 256, 256>>>(n);
    fill_kernel<<<(e4 + 255) / 256, 256>>>(src, dst, E);

    // 2) xs = dinv .* x   (also derives dinv from cursors)
    scale_x_kernel<<<(n * 16 + 255) / 256, 256>>>(x, d_xs, n);
    // 3) a[d] = xs[d] + sum_{s in N(d)} xs[s]    (64-ch gather)
    agg64_kernel<0><<<(n * 32 + 255) / 256, 256>>>(d_xs, nullptr, d_a, n);
    // 4) o1 = relu(dinv .* (a @ W1) + b1)        (64 -> 128)
    //    channel pairs: 64, TY=2, RR=4 -> 128 threads, 8 rows/pass, smem 36KB
    gemm_kernel<INC1, HIDC, 2, 4, 64, 1><<<(n + 63) / 64, dim3(HIDC / 2, 2)>>>(d_a, W1, b1, d_o1, n);
    // 5) g2 = dinv .* (o1 @ W2)                  (128 -> 64), reuse xs buffer
    //    channel pairs: 32, TY=4, RR=2 -> 128 threads, 8 rows/pass, smem 40KB
    gemm_kernel<HIDC, OUTC2, 4, 2, 64, 0><<<(n + 63) / 64, dim3(OUTC2 / 2, 4)>>>(d_o1, W2, nullptr, d_xs, n);
    // 6) out[d] = dinv[d] * (g2[d] + sum g2[s]) + b2   (64-ch gather)
    agg64_kernel<1><<<(n * 32 + 255) / 256, 256>>>(d_xs, b2, out, n);
}

// round 16
// speedup vs baseline: 1.1231x; 1.1231x over previous
#include <cuda_runtime.h>
#include <cuda_bf16.h>

// Problem constants (fixed by the dataset)
#define MAXN 100000
#define MAXE 3200000
#define INC1 64
#define HIDC 128
#define OUTC2 64
#define CAP 128              // per-node bucket capacity; in-deg ~ Poisson(32), P(>128) ~ 1e-40

// Packed fp32x2 ops (sm_100+; ptxas never emits these from C++)
#define ADDF32X2(acc, a) \
    asm("add.rn.f32x2 %0, %0, %1;" : "+l"(acc) : "l"(a))
#define FMAF32X2(acc, x, w) \
    asm("fma.rn.f32x2 %0, %1, %2, %0;" : "+l"(acc) : "l"(x), "l"(w))
#define UNPACK2(lo, hi, p) \
    asm("mov.b64 {%0, %1}, %2;" : "=f"(lo), "=f"(hi) : "l"(p))

// ---------------- device scratch (no allocations allowed) ----------------
__device__ float g_buf_o1[MAXN * HIDC];  // relu(layer1 output)            [N,128]
__device__ float g_buf_xs[MAXN * INC1];  // dinv*x, later reused for g2     [N,64]
__device__ float g_buf_a [MAXN * INC1];  // aggregated xs                   [N,64]
__device__ int   g_cursor[MAXN];         // absolute write cursor per bucket
__device__ int   g_col[MAXN * CAP];      // bucketed adjacency (src ids)
__device__ float g_dinv[MAXN];

// ---------------- bucket build ----------------
__global__ void init_cursor_kernel(int n) {
    int i = blockIdx.x * blockDim.x + threadIdx.x;
    if (i < n) g_cursor[i] = i * CAP;
}

// 4 edges per thread via int4 loads; atomic cursor allocates bucket slots.
__global__ void fill_kernel(const int* __restrict__ src,
                            const int* __restrict__ dst, int E) {
    int i = blockIdx.x * blockDim.x + threadIdx.x;
    int e = i << 2;
    if (e + 3 < E) {
        int4 s4 = *reinterpret_cast<const int4*>(src + e);
        int4 d4 = *reinterpret_cast<const int4*>(dst + e);
        g_col[atomicAdd(&g_cursor[d4.x], 1)] = s4.x;
        g_col[atomicAdd(&g_cursor[d4.y], 1)] = s4.y;
        g_col[atomicAdd(&g_cursor[d4.z], 1)] = s4.z;
        g_col[atomicAdd(&g_cursor[d4.w], 1)] = s4.w;
    } else if (e < E) {
        for (int k = e; k < E; k++)
            g_col[atomicAdd(&g_cursor[dst[k]], 1)] = src[k];
    }
}

// ---------------- xs = dinv .* x  (also materializes dinv from cursor) ----------------
__global__ void scale_x_kernel(const float* __restrict__ X, float* __restrict__ XS, int n) {
    int i = blockIdx.x * blockDim.x + threadIdx.x;      // one float4 per thread
    if (i >= n * 16) return;
    int row = i >> 4;
    int cnt = g_cursor[row] - row * CAP;                // in-degree (no self loop)
    float di = rsqrtf((float)(cnt + 1));
    if ((i & 15) == 0) g_dinv[row] = di;
    float4 v = ((const float4*)X)[i];
    v.x *= di; v.y *= di; v.z *= di; v.w *= di;
    ((float4*)XS)[i] = v;
}

// ---------------- Aggregation (bucket gather), one warp per node, 64 ch ----------------
// R13-measured-best: int4 index fetch, software pipelining, packed f32x2 adds.
template <int EPI>
__global__ void __launch_bounds__(256)
agg64_kernel(const float* __restrict__ G, const float* __restrict__ b,
             float* __restrict__ O, int n) {
    int warp = (blockIdx.x * blockDim.x + threadIdx.x) >> 5;
    int lane = threadIdx.x & 31;
    if (warp >= n) return;
    const int d = warp;
    const unsigned long long* __restrict__ Gv = (const unsigned long long*)G;
    unsigned long long acc = Gv[d * 32 + lane];          // self loop (packed f32x2)
    int e = d * CAP;
    const int end = g_cursor[d];
    int4 s;
    bool have = (e + 4 <= end);
    if (have) s = *reinterpret_cast<const int4*>(g_col + e);
    while (have) {
        int4 c = s;
        e += 4;
        have = (e + 4 <= end);
        if (have) s = *reinterpret_cast<const int4*>(g_col + e);
        unsigned long long a0 = Gv[c.x * 32 + lane];
        unsigned long long a1 = Gv[c.y * 32 + lane];
        unsigned long long a2 = Gv[c.z * 32 + lane];
        unsigned long long a3 = Gv[c.w * 32 + lane];
        ADDF32X2(acc, a0);
        ADDF32X2(acc, a1);
        ADDF32X2(acc, a2);
        ADDF32X2(acc, a3);
    }
    for (; e < end; e++) {
        int si = g_col[e];
        unsigned long long a = Gv[si * 32 + lane];
        ADDF32X2(acc, a);
    }
    float2 r;
    UNPACK2(r.x, r.y, acc);
    if (EPI) {
        const float di = g_dinv[d];
        float2 bi = ((const float2*)b)[lane];
        r.x = di * r.x + bi.x;
        r.y = di * r.y + bi.y;
    }
    ((float2*)O)[d * 32 + lane] = r;
}

// ---------------- GEMM, k-pair packed FFMA2 ----------------
// R13 thread map and X staging (unchanged). Accumulator holds {even-k, odd-k}
// partial sums; collapsed lo+hi once at the end.
//   xp = {x[k],x[k+1]}: contiguous in row-major Xs -> one broadcast LDS.64.
//   wp = {w[k],w[k+1]}: from W transposed with row stride INC+2 (== 2 mod 32),
//        lane banks 2l mod 32 -> each 16-lane phase covers all banks once:
//        conflict-free LDS.64.
// Per 2 k's: (1+RR) LDS.64 + RR FFMA2  (R13: 2+2RR LDS + 2RR FFMA).
// EPI=1: relu(dinv*acc + b) ; EPI=0: dinv*acc
template <int INC, int OUTC, int TY, int RR, int RPB, int EPI>
__global__ void __launch_bounds__(OUTC * TY)
gemm_kernel(const float* __restrict__ X, const float* __restrict__ W,
            const float* __restrict__ b, float* __restrict__ G, int n) {
    const int WSP = INC + 2;                 // stride == 2 (mod 32): conflict-free LDS.64
    __shared__ __align__(16) float Wt[OUTC * WSP];
    __shared__ __align__(16) float Xs[TY * RR][INC];
    const int tx = threadIdx.x;              // output channel
    const int ty = threadIdx.y;
    const int tid = ty * OUTC + tx;
    const int nthr = OUTC * TY;
    for (int i = tid; i < INC * OUTC; i += nthr) {
        int k = i / OUTC, c = i % OUTC;
        Wt[c * WSP + k] = W[i];
    }
    __syncthreads();
    const int ROWS = TY * RR;
    const int base = blockIdx.x * RPB;
    const float* wrow = &Wt[tx * WSP];
    for (int r0 = 0; r0 < RPB; r0 += ROWS) {
        for (int i = tid; i < ROWS * (INC / 4); i += nthr) {
            int rloc = i / (INC / 4);
            int cc = (i % (INC / 4));
            int rr = base + r0 + rloc;
            float4 v = (rr < n) ? ((const float4*)(X + rr * INC))[cc]
                                : make_float4(0.f, 0.f, 0.f, 0.f);
            *(float4*)&Xs[rloc][cc * 4] = v;
        }
        __syncthreads();
        unsigned long long acc2[RR];
#pragma unroll
        for (int r = 0; r < RR; r++) acc2[r] = 0ull;     // packed (+0,+0)
#pragma unroll 8
        for (int k2 = 0; k2 < INC / 2; k2++) {
            unsigned long long wp = *(const unsigned long long*)(wrow + 2 * k2);
#pragma unroll
            for (int r = 0; r < RR; r++) {
                unsigned long long xp =
                    *(const unsigned long long*)&Xs[ty * RR + r][2 * k2];
                FMAF32X2(acc2[r], xp, wp);
            }
        }
#pragma unroll
        for (int r = 0; r < RR; r++) {
            int row = base + r0 + ty * RR + r;
            if (row < n) {
                float lo, hi;
                UNPACK2(lo, hi, acc2[r]);
                float acc = lo + hi;
                float di = g_dinv[row];
                float v = EPI ? fmaxf(di * acc + b[tx], 0.f) : di * acc;
                G[row * OUTC + tx] = v;
            }
        }
        __syncthreads();
    }
}

// ---------------- launch ----------------
extern "C" void kernel_launch(void* const* d_in, const int* in_sizes, int n_in,
                              void* d_out, int out_size) {
    const float* x  = (const float*)d_in[0];
    const int*   ei = (const int*)d_in[1];     // int32 (JAX x64-disabled truncates int64)
    const float* W1 = (const float*)d_in[2];
    const float* b1 = (const float*)d_in[3];
    const float* W2 = (const float*)d_in[4];
    const float* b2 = (const float*)d_in[5];
    float* out = (float*)d_out;

    const int n = in_sizes[0] / INC1;     // 100000
    const int E = in_sizes[1] / 2;        // 3200000
    const int* src = ei;
    const int* dst = ei + E;
    const int e4 = (E + 3) / 4;

    float* d_o1 = nullptr; cudaGetSymbolAddress((void**)&d_o1, g_buf_o1);
    float* d_xs = nullptr; cudaGetSymbolAddress((void**)&d_xs, g_buf_xs);
    float* d_a  = nullptr; cudaGetSymbolAddress((void**)&d_a,  g_buf_a);

    // 1) bucketed adjacency build (no count pass, no scan)
    init_cursor_kernel<<<(n + 255) / 256, 256>>>(n);
    fill_kernel<<<(e4 + 255) / 256, 256>>>(src, dst, E);

    // 2) xs = dinv .* x   (also derives dinv from cursors)
    scale_x_kernel<<<(n * 16 + 255) / 256, 256>>>(x, d_xs, n);
    // 3) a[d] = xs[d] + sum_{s in N(d)} xs[s]    (64-ch gather)
    agg64_kernel<0><<<(n * 32 + 255) / 256, 256>>>(d_xs, nullptr, d_a, n);
    // 4) o1 = relu(dinv .* (a @ W1) + b1)        (64 -> 128)
    gemm_kernel<INC1, HIDC, 2, 4, 64, 1><<<(n + 63) / 64, dim3(HIDC, 2)>>>(d_a, W1, b1, d_o1, n);
    // 5) g2 = dinv .* (o1 @ W2)                  (128 -> 64), reuse xs buffer
    gemm_kernel<HIDC, OUTC2, 4, 4, 64, 0><<<(n + 63) / 64, dim3(OUTC2, 4)>>>(d_o1, W2, nullptr, d_xs, n);
    // 6) out[d] = dinv[d] * (g2[d] + sum g2[s]) + b2   (64-ch gather)
    agg64_kernel<1><<<(n * 32 + 255) / 256, 256>>>(d_xs, b2, out, n);
}